// round 10
// baseline (speedup 1.0000x reference)
#include <cuda_runtime.h>
#include <math.h>
#include <math_constants.h>

#define C_CLASSES 1000
#define NVEC      (C_CLASSES / 4)   // 250 float4 per row
#define THREADS   256
#define WPB       (THREADS / 32)
#define NBLK      592               // 4 blocks/SM * 148 SMs = one full wave
#define MAGIC     0.165745444183859f

__device__ float g_partials[NBLK];

// ---------------------------------------------------------------------------
// Main kernel: fused scalar prep + pipelined per-row logsumexp with margin.
// One deterministic partial per block. No atomics, no cross-block sync.
// ---------------------------------------------------------------------------
__global__ void __launch_bounds__(THREADS, 4)
fused_loss_kernel(const float* __restrict__ x,
                  const int*   __restrict__ targets,
                  const float* __restrict__ cls,
                  const float* __restrict__ diff,
                  const int*   __restrict__ epoch_p,
                  int nB, int nC)
{
    const int tid  = threadIdx.x;
    const int lane = tid & 31;
    const int wid  = tid >> 5;

    const int gwarp = blockIdx.x * WPB + wid;
    const int totw  = gridDim.x * WPB;

    // ---- Prefetch row 0 BEFORE the prep barrier (hides prep latency) ------
    int    row  = gwarp;
    bool   have = (row < nB);
    float4 v[8];
    float  xt = 0.0f, ct = 1.0f, dt = 0.0f;   // per-row pipelined scalars
    if (have) {
        const int t = __ldg(targets + row);
        const float* xrow = x + (size_t)row * C_CLASSES;
        xt = __ldg(xrow + t);                  // warp-uniform target logit
        ct = __ldg(cls + t);
        dt = __ldg(diff + t);
        const float4* xr = reinterpret_cast<const float4*>(xrow);
        #pragma unroll
        for (int j = 0; j < 7; j++)
            v[j] = __ldg(xr + lane + 32 * j);
        int idx = lane + 224;
        if (idx < NVEC) v[7] = __ldg(xr + idx);
        else            v[7] = make_float4(-1e30f, -1e30f, -1e30f, -1e30f);
    }

    // ---- Phase 0: per-block redundant scalar prep (L2-hot, ~1000 elems) ---
    __shared__ float s_mn[WPB], s_sm[WPB], s_mx[WPB];
    __shared__ float s_scalars[3];
    {
        float mn = CUDART_INF_F, sm = 0.0f, mx = -CUDART_INF_F;
        for (int i = tid; i < nC; i += THREADS) {
            float c = __ldg(cls + i);
            float d = __ldg(diff + i);
            mn = fminf(mn, c);
            sm += c;
            mx = fmaxf(mx, 0.5f * d * d + 0.3f);
        }
        #pragma unroll
        for (int o = 16; o; o >>= 1) {
            mn = fminf(mn, __shfl_xor_sync(0xffffffffu, mn, o));
            sm += __shfl_xor_sync(0xffffffffu, sm, o);
            mx = fmaxf(mx, __shfl_xor_sync(0xffffffffu, mx, o));
        }
        if (lane == 0) { s_mn[wid] = mn; s_sm[wid] = sm; s_mx[wid] = mx; }
        __syncthreads();
        if (tid == 0) {
            mn = s_mn[0]; sm = s_sm[0]; mx = s_mx[0];
            #pragma unroll
            for (int i = 1; i < WPB; i++) {
                mn = fminf(mn, s_mn[i]);
                sm += s_sm[i];
                mx = fmaxf(mx, s_mx[i]);
            }
            s_scalars[0] = mn; s_scalars[1] = sm; s_scalars[2] = mx;
        }
        __syncthreads();
    }

    const float min_c = s_scalars[0];
    const float sum_c = s_scalars[1];
    const float wmax  = s_scalars[2];
    const float max_m = -logf(min_c / sum_c) - MAGIC;

    const int epoch = epoch_p ? __ldg(epoch_p) : 70;
    float ee = 0.0f;
    if (epoch >= 60) ee = (epoch >= 80) ? 1.0f : (float)(epoch - 60) * (1.0f / 20.0f);
    const float wscale = ee * 0.5f * max_m / wmax;   // multiplies (0.5 d^2 + 0.3)

    // ---- Phase 1: stream rows, software-pipelined -------------------------
    float acc = 0.0f;

    #pragma unroll 1
    while (have) {
        // Row max (no exp in the dependency chain).
        float m = -CUDART_INF_F;
        #pragma unroll
        for (int j = 0; j < 8; j++)
            m = fmaxf(m, fmaxf(fmaxf(v[j].x, v[j].y), fmaxf(v[j].z, v[j].w)));
        #pragma unroll
        for (int o = 16; o; o >>= 1)
            m = fmaxf(m, __shfl_xor_sync(0xffffffffu, m, o));

        // Independent exps (last read of v).
        float s = 0.0f;
        #pragma unroll
        for (int j = 0; j < 8; j++) {
            s += __expf(v[j].x - m) + __expf(v[j].y - m)
               + __expf(v[j].z - m) + __expf(v[j].w - m);
        }

        // v is dead: prefetch next row NOW so the tail math below overlaps
        // the DRAM latency of these loads.
        const float xt_c = xt, ct_c = ct, dt_c = dt;
        row += totw;
        have = (row < nB);
        if (have) {
            const int t = __ldg(targets + row);
            const float* xrow = x + (size_t)row * C_CLASSES;
            xt = __ldg(xrow + t);
            ct = __ldg(cls + t);
            dt = __ldg(diff + t);
            const float4* xr = reinterpret_cast<const float4*>(xrow);
            #pragma unroll
            for (int j = 0; j < 7; j++)
                v[j] = __ldg(xr + lane + 32 * j);
            int idx = lane + 224;
            if (idx < NVEC) v[7] = __ldg(xr + idx);
            else            v[7] = make_float4(-1e30f, -1e30f, -1e30f, -1e30f);
        }

        // Finish current row under the prefetch latency.
        #pragma unroll
        for (int o = 16; o; o >>= 1)
            s += __shfl_xor_sync(0xffffffffu, s, o);

        const float margin = max_m * sqrtf(min_c / ct_c)
                           + (0.5f * dt_c * dt_c + 0.3f) * wscale;
        const float xta  = xt_c - margin;
        // s' = s - e^{xt-m} + e^{xt-margin-m} = s + e^{xt-m} (e^{-margin} - 1)
        const float sadj = s + __expf(xt_c - m) * (__expf(-margin) - 1.0f);
        acc += (m + __logf(sadj)) - xta;
    }

    // ---- Phase 2: block partial (deterministic, no atomics) ---------------
    __shared__ float sacc[WPB];
    if (lane == 0) sacc[wid] = acc;
    __syncthreads();
    if (tid == 0) {
        float tot = 0.0f;
        #pragma unroll
        for (int i = 0; i < WPB; i++) tot += sacc[i];
        g_partials[blockIdx.x] = tot;
    }
}

// ---------------------------------------------------------------------------
// Finalize: reduce NBLK partials -> mean loss. One block.
// ---------------------------------------------------------------------------
__global__ void finalize_kernel(float* __restrict__ out, int nB) {
    __shared__ float sh[THREADS / 32];
    int tid = threadIdx.x;
    float v = 0.0f;
    for (int i = tid; i < NBLK; i += THREADS)
        v += g_partials[i];
    #pragma unroll
    for (int o = 16; o; o >>= 1)
        v += __shfl_xor_sync(0xffffffffu, v, o);
    if ((tid & 31) == 0) sh[tid >> 5] = v;
    __syncthreads();
    if (tid < 32) {
        v = (tid < THREADS / 32) ? sh[tid] : 0.0f;
        #pragma unroll
        for (int o = 16; o; o >>= 1)
            v += __shfl_xor_sync(0xffffffffu, v, o);
        if (tid == 0) out[0] = v / (float)nB;
    }
}

// ---------------------------------------------------------------------------
extern "C" void kernel_launch(void* const* d_in, const int* in_sizes, int n_in,
                              void* d_out, int out_size) {
    const float* x       = (const float*)d_in[0];
    const int*   targets = (const int*)  d_in[1];
    const float* cls     = (const float*)d_in[2];
    const float* diff    = (const float*)d_in[3];
    const int*   epoch   = (n_in >= 5) ? (const int*)d_in[4] : nullptr;

    int nB = in_sizes[1];
    int nC = in_sizes[2];
    float* out = (float*)d_out;

    fused_loss_kernel<<<NBLK, THREADS>>>(x, targets, cls, diff, epoch, nB, nC);
    finalize_kernel<<<1, THREADS>>>(out, nB);
}